// round 3
// baseline (speedup 1.0000x reference)
#include <cuda_runtime.h>
#include <cstdint>
#include <cstddef>

#define N_NODES 100000
#define N_FEAT  512
#define HIDDEN  64
#define N_CLASS 40
#define MAX_E   3200000

// ---------------- scratch (device globals; no allocations allowed) ----------
__device__ float g_deg [N_NODES];
__device__ float g_dinv[N_NODES];
__device__ float g_h1  [(size_t)N_NODES * HIDDEN];
__device__ float g_agg1[(size_t)N_NODES * HIDDEN];
__device__ float g_h2  [(size_t)N_NODES * N_CLASS];
__device__ float g_agg2[(size_t)N_NODES * N_CLASS];
__device__ int   g_src [MAX_E];
__device__ int   g_dst [MAX_E];
__device__ int   g_is64;

// ---------------- dtype detection: int64 vs int32 edge_index ----------------
// If int64 (little-endian, values in [0, 1e5)), every odd 32-bit word is 0.
__global__ void detect_kernel(const int* __restrict__ ei, int E) {
    __shared__ int any_nonzero;
    if (threadIdx.x == 0) any_nonzero = 0;
    __syncthreads();
    int nchk = E < 2048 ? E : 2048;
    for (int i = threadIdx.x; i < nchk; i += blockDim.x)
        if (ei[2 * i + 1] != 0) any_nonzero = 1;
    __syncthreads();
    if (threadIdx.x == 0) g_is64 = (any_nonzero == 0) ? 1 : 0;
}

__global__ void convert_edges_kernel(const void* __restrict__ ei, int E) {
    int e = blockIdx.x * blockDim.x + threadIdx.x;
    if (e >= E) return;
    if (g_is64) {
        const long long* p = (const long long*)ei;
        g_src[e] = (int)p[e];
        g_dst[e] = (int)p[(size_t)E + e];
    } else {
        const int* p = (const int*)ei;
        g_src[e] = p[e];
        g_dst[e] = p[(size_t)E + e];
    }
}

// ---------------- init: deg=1 (self loop), zero accumulators ----------------
__global__ void init_kernel() {
    int i = blockIdx.x * blockDim.x + threadIdx.x;
    if (i < N_NODES * HIDDEN)  g_agg1[i] = 0.f;
    if (i < N_NODES * N_CLASS) g_agg2[i] = 0.f;
    if (i < N_NODES)           g_deg[i]  = 1.0f;
}

__global__ void degree_kernel(int E) {
    int e = blockIdx.x * blockDim.x + threadIdx.x;
    if (e < E) atomicAdd(&g_deg[g_dst[e]], 1.0f);
}

__global__ void dinv_kernel() {
    int i = blockIdx.x * blockDim.x + threadIdx.x;
    if (i < N_NODES) g_dinv[i] = rsqrtf(g_deg[i]);
}

// ---------------- GEMM1: h1 = x @ W1  (100000x512 @ 512x64) -----------------
// 64 nodes x 64 cols per block, 256 threads, K-chunks of 32.
__global__ __launch_bounds__(256) void gemm1_kernel(
    const float* __restrict__ x, const float* __restrict__ W1, int N)
{
    __shared__ float xs[64 * 32];
    __shared__ float ws[32 * 64];
    int tid = threadIdx.x;
    int nb  = blockIdx.x * 64;
    int tx  = tid & 15;      // col group (4 cols via float4)
    int ty  = tid >> 4;      // row group (4 rows)

    float acc[4][4];
    #pragma unroll
    for (int i = 0; i < 4; i++)
        #pragma unroll
        for (int j = 0; j < 4; j++) acc[i][j] = 0.f;

    for (int kc = 0; kc < N_FEAT; kc += 32) {
        // x tile: 64 rows x 32 cols = 512 float4
        #pragma unroll
        for (int l = 0; l < 2; l++) {
            int e  = tid + l * 256;
            int r  = e >> 3, c4 = e & 7;
            float4 v = make_float4(0.f, 0.f, 0.f, 0.f);
            int node = nb + r;
            if (node < N)
                v = *(const float4*)(x + (size_t)node * N_FEAT + kc + c4 * 4);
            *(float4*)(xs + r * 32 + c4 * 4) = v;
        }
        // W tile: 32 rows x 64 cols = 512 float4
        #pragma unroll
        for (int l = 0; l < 2; l++) {
            int e  = tid + l * 256;
            int r  = e >> 4, c4 = e & 15;
            *(float4*)(ws + r * 64 + c4 * 4) =
                *(const float4*)(W1 + (size_t)(kc + r) * HIDDEN + c4 * 4);
        }
        __syncthreads();
        #pragma unroll
        for (int kk = 0; kk < 32; kk++) {
            float4 b = *(const float4*)(ws + kk * 64 + tx * 4);
            float  a[4];
            #pragma unroll
            for (int i = 0; i < 4; i++) a[i] = xs[(ty * 4 + i) * 32 + kk];
            #pragma unroll
            for (int i = 0; i < 4; i++) {
                acc[i][0] += a[i] * b.x;
                acc[i][1] += a[i] * b.y;
                acc[i][2] += a[i] * b.z;
                acc[i][3] += a[i] * b.w;
            }
        }
        __syncthreads();
    }
    #pragma unroll
    for (int i = 0; i < 4; i++) {
        int node = nb + ty * 4 + i;
        if (node < N) {
            float4 v = make_float4(acc[i][0], acc[i][1], acc[i][2], acc[i][3]);
            *(float4*)(g_h1 + (size_t)node * HIDDEN + tx * 4) = v;
        }
    }
}

// ---------------- scatter layer 1: agg1[dst] += w * h1[src] -----------------
// 16 lanes per edge, each lane one float4 (64 floats/edge).
__global__ __launch_bounds__(256) void scatter1_kernel(int E) {
    unsigned gid = blockIdx.x * blockDim.x + threadIdx.x;
    int e = gid >> 4, c = gid & 15;
    if (e >= E) return;
    int s = g_src[e], d = g_dst[e];
    float w = g_dinv[s] * g_dinv[d];
    float4 v = ((const float4*)(g_h1 + (size_t)s * HIDDEN))[c];
    atomicAdd(&((float4*)(g_agg1 + (size_t)d * HIDDEN))[c],
              make_float4(w * v.x, w * v.y, w * v.z, w * v.w));
}

// ---- layer 2: a = relu(agg1 + dinv^2*h1 + b1); h2 = a @ W2 (64x40) ---------
__global__ __launch_bounds__(160) void layer2_kernel(
    const float* __restrict__ b1, const float* __restrict__ W2, int N)
{
    __shared__ float a  [32 * 64];
    __shared__ float w2s[64 * 40];
    __shared__ float b1s[64];
    int tid = threadIdx.x;
    int nb  = blockIdx.x * 32;

    for (int i = tid; i < 64 * 40; i += 160) w2s[i] = W2[i];
    if (tid < 64) b1s[tid] = b1[tid];
    __syncthreads();

    for (int i = tid; i < 32 * 64; i += 160) {
        int r = i >> 6, k = i & 63;
        int node = nb + r;
        float v = 0.f;
        if (node < N) {
            float di = g_dinv[node];
            v = g_agg1[(size_t)node * 64 + k]
              + di * di * g_h1[(size_t)node * 64 + k] + b1s[k];
            v = fmaxf(v, 0.f);
        }
        a[i] = v;
    }
    __syncthreads();

    int c = tid % 40;       // output class
    int g = tid / 40;       // node subgroup 0..3
    float acc[8];
    #pragma unroll
    for (int i = 0; i < 8; i++) acc[i] = 0.f;
    #pragma unroll
    for (int k = 0; k < 64; k++) {
        float w = w2s[k * 40 + c];
        #pragma unroll
        for (int i = 0; i < 8; i++)
            acc[i] += a[(g + i * 4) * 64 + k] * w;
    }
    #pragma unroll
    for (int i = 0; i < 8; i++) {
        int node = nb + g + i * 4;
        if (node < N) g_h2[(size_t)node * N_CLASS + c] = acc[i];
    }
}

// ---------------- scatter layer 2: agg2[dst] += w * h2[src] -----------------
// 16 lanes per edge, lanes 0..9 active (40 floats = 10 float4).
__global__ __launch_bounds__(256) void scatter2_kernel(int E) {
    unsigned gid = blockIdx.x * blockDim.x + threadIdx.x;
    int e = gid >> 4, c = gid & 15;
    if (e >= E || c >= 10) return;
    int s = g_src[e], d = g_dst[e];
    float w = g_dinv[s] * g_dinv[d];
    float4 v = ((const float4*)(g_h2 + (size_t)s * N_CLASS))[c];
    atomicAdd(&((float4*)(g_agg2 + (size_t)d * N_CLASS))[c],
              make_float4(w * v.x, w * v.y, w * v.z, w * v.w));
}

// ---------------- final: self-loop + b2 + softmax ---------------------------
__global__ __launch_bounds__(256) void final_kernel(
    const float* __restrict__ b2, float* __restrict__ out, int N)
{
    int node = blockIdx.x * blockDim.x + threadIdx.x;
    if (node >= N) return;
    float di = g_dinv[node];
    float d2 = di * di;
    const float* a2 = g_agg2 + (size_t)node * N_CLASS;
    const float* h2 = g_h2   + (size_t)node * N_CLASS;
    float v[N_CLASS];
    float m = -1e30f;
    #pragma unroll
    for (int j = 0; j < N_CLASS; j++) {
        v[j] = a2[j] + d2 * h2[j] + b2[j];
        m = fmaxf(m, v[j]);
    }
    float s = 0.f;
    #pragma unroll
    for (int j = 0; j < N_CLASS; j++) {
        v[j] = expf(v[j] - m);
        s += v[j];
    }
    float inv = 1.f / s;
    #pragma unroll
    for (int j = 0; j < N_CLASS; j++)
        out[(size_t)node * N_CLASS + j] = v[j] * inv;
}

// ---------------- launch -----------------------------------------------------
extern "C" void kernel_launch(void* const* d_in, const int* in_sizes, int n_in,
                              void* d_out, int out_size)
{
    const float* x   = (const float*)d_in[0];
    const void*  ei  = d_in[1];
    const float* W1  = (const float*)d_in[2];
    const float* b1  = (const float*)d_in[3];
    const float* W2  = (const float*)d_in[4];
    const float* b2  = (const float*)d_in[5];
    float* out = (float*)d_out;

    int N = in_sizes[0] / N_FEAT;       // 100000
    int E = in_sizes[1] / 2;            // 3200000 (element count same for i32/i64)

    detect_kernel<<<1, 256>>>((const int*)ei, E);
    convert_edges_kernel<<<(E + 255) / 256, 256>>>(ei, E);

    int initN = N_NODES * HIDDEN;
    init_kernel<<<(initN + 255) / 256, 256>>>();

    degree_kernel<<<(E + 255) / 256, 256>>>(E);
    dinv_kernel<<<(N + 255) / 256, 256>>>();

    gemm1_kernel<<<(N + 63) / 64, 256>>>(x, W1, N);

    long long t1 = (long long)E * 16;
    scatter1_kernel<<<(unsigned)((t1 + 255) / 256), 256>>>(E);

    layer2_kernel<<<(N + 31) / 32, 160>>>(b1, W2, N);

    scatter2_kernel<<<(unsigned)((t1 + 255) / 256), 256>>>(E);

    final_kernel<<<(N + 255) / 256, 256>>>(b2, out, N);
}

// round 6
// speedup vs baseline: 1.2053x; 1.2053x over previous
#include <cuda_runtime.h>
#include <cstdint>
#include <cstddef>

#define N_NODES 100000
#define N_FEAT  512
#define HIDDEN  64
#define N_CLASS 40
#define MAX_E   3200000
#define SCAN_B  512
#define NB_SCAN ((N_NODES + SCAN_B - 1) / SCAN_B)   // 196

typedef unsigned long long ull;

// ---------------- scratch (device globals; no allocations allowed) ----------
__device__ float g_dinv  [N_NODES];
__device__ float g_h1    [(size_t)N_NODES * HIDDEN];
__device__ float g_a     [(size_t)N_NODES * HIDDEN];
__device__ float g_h2    [(size_t)N_NODES * N_CLASS];
__device__ int   g_src   [MAX_E];
__device__ int   g_dst   [MAX_E];
__device__ int   g_csr   [MAX_E];
__device__ int   g_cnt   [N_NODES];
__device__ int   g_cur   [N_NODES];
__device__ int   g_rowptr[N_NODES + 1];
__device__ int   g_bsum  [NB_SCAN];
__device__ int   g_is64;

// ---------------- helpers ---------------------------------------------------
__device__ __forceinline__ void ffma2(ull& d, ull a, ull b, ull c) {
    asm("fma.rn.f32x2 %0, %1, %2, %3;" : "=l"(d) : "l"(a), "l"(b), "l"(c));
}
__device__ __forceinline__ float2 u2f(ull u) {
    float2 f;
    asm("mov.b64 {%0,%1}, %2;" : "=f"(f.x), "=f"(f.y) : "l"(u));
    return f;
}

// ---------------- dtype detection: int64 vs int32 edge_index ----------------
__global__ void detect_kernel(const int* __restrict__ ei, int E) {
    __shared__ int any_nonzero;
    if (threadIdx.x == 0) any_nonzero = 0;
    __syncthreads();
    int nchk = E < 2048 ? E : 2048;
    for (int i = threadIdx.x; i < nchk; i += blockDim.x)
        if (ei[2 * i + 1] != 0) any_nonzero = 1;
    __syncthreads();
    if (threadIdx.x == 0) g_is64 = (any_nonzero == 0) ? 1 : 0;
}

__global__ void zero_kernel() {
    int i = blockIdx.x * blockDim.x + threadIdx.x;
    if (i < N_NODES) { g_cnt[i] = 0; g_cur[i] = 0; }
}

// ---------------- convert edges + count in-degree ---------------------------
__global__ void convert_count_kernel(const void* __restrict__ ei, int E) {
    int e = blockIdx.x * blockDim.x + threadIdx.x;
    if (e >= E) return;
    int s, d;
    if (g_is64) {
        const long long* p = (const long long*)ei;
        s = (int)p[e]; d = (int)p[(size_t)E + e];
    } else {
        const int* p = (const int*)ei;
        s = p[e]; d = p[(size_t)E + e];
    }
    g_src[e] = s;
    g_dst[e] = d;
    atomicAdd(&g_cnt[d], 1);
}

// ---------------- 3-pass exclusive scan of g_cnt -> g_rowptr ----------------
__global__ void scan1_kernel() {
    __shared__ int s[SCAN_B];
    int b = blockIdx.x, t = threadIdx.x, i = b * SCAN_B + t;
    int v = (i < N_NODES) ? g_cnt[i] : 0;
    s[t] = v; __syncthreads();
    #pragma unroll
    for (int o = 1; o < SCAN_B; o <<= 1) {
        int add = (t >= o) ? s[t - o] : 0;
        __syncthreads();
        s[t] += add;
        __syncthreads();
    }
    if (i < N_NODES) g_rowptr[i] = s[t] - v;       // local exclusive
    if (t == SCAN_B - 1) g_bsum[b] = s[t];
}
__global__ void scan2_kernel() {
    __shared__ int s[256];
    int t = threadIdx.x;
    int v = (t < NB_SCAN) ? g_bsum[t] : 0;
    s[t] = v; __syncthreads();
    #pragma unroll
    for (int o = 1; o < 256; o <<= 1) {
        int add = (t >= o) ? s[t - o] : 0;
        __syncthreads();
        s[t] += add;
        __syncthreads();
    }
    if (t < NB_SCAN) g_bsum[t] = s[t] - v;         // exclusive block offsets
}
__global__ void scan3_kernel(int E) {
    int i = blockIdx.x * blockDim.x + threadIdx.x;
    if (i < N_NODES) {
        g_rowptr[i] += g_bsum[i / SCAN_B];
        g_dinv[i] = rsqrtf((float)g_cnt[i] + 1.0f);  // +1 self loop
    }
    if (i == 0) g_rowptr[N_NODES] = E;
}

// ---------------- bin edges into CSR ----------------------------------------
__global__ void bin_kernel(int E) {
    int e = blockIdx.x * blockDim.x + threadIdx.x;
    if (e >= E) return;
    int d = g_dst[e];
    int p = atomicAdd(&g_cur[d], 1);
    g_csr[g_rowptr[d] + p] = g_src[e];
}

// ---------------- GEMM1: h1 = x @ W1 (f32x2 packed FMA) ---------------------
// 128 nodes x 64 cols per block, 256 threads, BK=16.
// xs: k-major (row pairs contiguous -> direct f32x2 loads of A)
// ws2: each W value duplicated -> direct {b,b} f32x2 loads of B
#define BM 128
#define BKK 16
__global__ __launch_bounds__(256) void gemm1_kernel(
    const float* __restrict__ x, const float* __restrict__ W1, int N)
{
    __shared__ float xs[BKK][BM + 4];
    __shared__ float ws2[BKK][HIDDEN * 2];
    int tid = threadIdx.x;
    int nb  = blockIdx.x * BM;
    int tx  = tid & 15;      // 4 output cols: tx*4..tx*4+3
    int ty  = tid >> 4;      // 8 output rows: ty*8..ty*8+7

    ull acc[4][4];           // [row-pair][col]
    #pragma unroll
    for (int i = 0; i < 4; i++)
        #pragma unroll
        for (int j = 0; j < 4; j++) acc[i][j] = 0ULL;

    for (int kc = 0; kc < N_FEAT; kc += BKK) {
        // x tile: 128 rows x 16 k (transposed into xs)
        #pragma unroll
        for (int l = 0; l < 2; l++) {
            int e  = tid + l * 256;
            int k4 = e & 3, r = e >> 2;
            float4 v = make_float4(0.f, 0.f, 0.f, 0.f);
            int node = nb + r;
            if (node < N)
                v = *(const float4*)(x + (size_t)node * N_FEAT + kc + k4 * 4);
            xs[k4 * 4 + 0][r] = v.x;
            xs[k4 * 4 + 1][r] = v.y;
            xs[k4 * 4 + 2][r] = v.z;
            xs[k4 * 4 + 3][r] = v.w;
        }
        // W tile: 16 rows x 64 cols, duplicated
        {
            int r = tid >> 4, c4 = tid & 15;
            float4 v = *(const float4*)(W1 + (size_t)(kc + r) * HIDDEN + c4 * 4);
            int cb = c4 * 8;
            ws2[r][cb + 0] = v.x; ws2[r][cb + 1] = v.x;
            ws2[r][cb + 2] = v.y; ws2[r][cb + 3] = v.y;
            ws2[r][cb + 4] = v.z; ws2[r][cb + 5] = v.z;
            ws2[r][cb + 6] = v.w; ws2[r][cb + 7] = v.w;
        }
        __syncthreads();
        #pragma unroll
        for (int kk = 0; kk < BKK; kk++) {
            ulonglong2 a01 = *(const ulonglong2*)&xs[kk][ty * 8];
            ulonglong2 a23 = *(const ulonglong2*)&xs[kk][ty * 8 + 4];
            ulonglong2 b01 = *(const ulonglong2*)&ws2[kk][tx * 8];
            ulonglong2 b23 = *(const ulonglong2*)&ws2[kk][tx * 8 + 4];
            ull av[4] = {a01.x, a01.y, a23.x, a23.y};
            ull bv[4] = {b01.x, b01.y, b23.x, b23.y};
            #pragma unroll
            for (int i = 0; i < 4; i++)
                #pragma unroll
                for (int j = 0; j < 4; j++)
                    ffma2(acc[i][j], av[i], bv[j], acc[i][j]);
        }
        __syncthreads();
    }
    #pragma unroll
    for (int i = 0; i < 4; i++) {
        int r0 = nb + ty * 8 + i * 2;
        float2 p0 = u2f(acc[i][0]), p1 = u2f(acc[i][1]);
        float2 p2 = u2f(acc[i][2]), p3 = u2f(acc[i][3]);
        if (r0 < N) {
            float4 o = make_float4(p0.x, p1.x, p2.x, p3.x);
            *(float4*)(g_h1 + (size_t)r0 * HIDDEN + tx * 4) = o;
        }
        if (r0 + 1 < N) {
            float4 o = make_float4(p0.y, p1.y, p2.y, p3.y);
            *(float4*)(g_h1 + (size_t)(r0 + 1) * HIDDEN + tx * 4) = o;
        }
    }
}

// ------ gather layer 1: a = relu(sum_{s->d} w*h1[s] + dinv^2*h1[d] + b1) ----
// One warp per dst node; lane covers feats [2*lane, 2*lane+1].
__global__ __launch_bounds__(256) void gather1_kernel(
    const float* __restrict__ b1, int N)
{
    int gw   = (blockIdx.x * blockDim.x + threadIdx.x) >> 5;
    int lane = threadIdx.x & 31;
    if (gw >= N) return;
    int beg = g_rowptr[gw], end = g_rowptr[gw + 1];
    float dd = g_dinv[gw];
    float ax = 0.f, ay = 0.f;

    for (int j0 = beg; j0 < end; j0 += 32) {
        int n = min(32, end - j0);
        int sj = 0; float wj = 0.f;
        if (lane < n) { sj = g_csr[j0 + lane]; wj = g_dinv[sj] * dd; }
        int jj = 0;
        for (; jj + 4 <= n; jj += 4) {
            int   s0 = __shfl_sync(0xffffffffu, sj, jj);
            int   s1 = __shfl_sync(0xffffffffu, sj, jj + 1);
            int   s2 = __shfl_sync(0xffffffffu, sj, jj + 2);
            int   s3 = __shfl_sync(0xffffffffu, sj, jj + 3);
            float w0 = __shfl_sync(0xffffffffu, wj, jj);
            float w1 = __shfl_sync(0xffffffffu, wj, jj + 1);
            float w2 = __shfl_sync(0xffffffffu, wj, jj + 2);
            float w3 = __shfl_sync(0xffffffffu, wj, jj + 3);
            float2 v0 = *(const float2*)(g_h1 + (size_t)s0 * HIDDEN + lane * 2);
            float2 v1 = *(const float2*)(g_h1 + (size_t)s1 * HIDDEN + lane * 2);
            float2 v2 = *(const float2*)(g_h1 + (size_t)s2 * HIDDEN + lane * 2);
            float2 v3 = *(const float2*)(g_h1 + (size_t)s3 * HIDDEN + lane * 2);
            ax += w0 * v0.x; ay += w0 * v0.y;
            ax += w1 * v1.x; ay += w1 * v1.y;
            ax += w2 * v2.x; ay += w2 * v2.y;
            ax += w3 * v3.x; ay += w3 * v3.y;
        }
        for (; jj < n; jj++) {
            int   s = __shfl_sync(0xffffffffu, sj, jj);
            float w = __shfl_sync(0xffffffffu, wj, jj);
            float2 v = *(const float2*)(g_h1 + (size_t)s * HIDDEN + lane * 2);
            ax += w * v.x; ay += w * v.y;
        }
    }
    float2 hv = *(const float2*)(g_h1 + (size_t)gw * HIDDEN + lane * 2);
    float d2 = dd * dd;
    ax += d2 * hv.x; ay += d2 * hv.y;
    float2 bb = *(const float2*)(b1 + lane * 2);
    ax = fmaxf(ax + bb.x, 0.f);
    ay = fmaxf(ay + bb.y, 0.f);
    *(float2*)(g_a + (size_t)gw * HIDDEN + lane * 2) = make_float2(ax, ay);
}

// ---------------- layer 2 GEMM: h2 = a @ W2 (64x40) -------------------------
__global__ __launch_bounds__(160) void layer2_kernel(
    const float* __restrict__ W2, int N)
{
    __shared__ float a  [32 * 64];
    __shared__ float w2s[64 * 40];
    int tid = threadIdx.x;
    int nb  = blockIdx.x * 32;

    for (int i = tid; i < 64 * 40; i += 160) w2s[i] = W2[i];
    __syncthreads();

    for (int i = tid; i < 32 * 64; i += 160) {
        int r = i >> 6, k = i & 63;
        int node = nb + r;
        a[i] = (node < N) ? g_a[(size_t)node * 64 + k] : 0.f;
    }
    __syncthreads();

    int c = tid % 40;
    int g = tid / 40;
    float acc[8];
    #pragma unroll
    for (int i = 0; i < 8; i++) acc[i] = 0.f;
    #pragma unroll
    for (int k = 0; k < 64; k++) {
        float w = w2s[k * 40 + c];
        #pragma unroll
        for (int i = 0; i < 8; i++)
            acc[i] += a[(g + i * 4) * 64 + k] * w;
    }
    #pragma unroll
    for (int i = 0; i < 8; i++) {
        int node = nb + g + i * 4;
        if (node < N) g_h2[(size_t)node * N_CLASS + c] = acc[i];
    }
}

// ------ gather layer 2 + b2 + softmax (fused final) -------------------------
// One warp per dst node; lanes 0..19 each cover feats [2*lane, 2*lane+1].
__global__ __launch_bounds__(256) void gather2_kernel(
    const float* __restrict__ b2, float* __restrict__ out, int N)
{
    int gw   = (blockIdx.x * blockDim.x + threadIdx.x) >> 5;
    int lane = threadIdx.x & 31;
    if (gw >= N) return;
    int beg = g_rowptr[gw], end = g_rowptr[gw + 1];
    float dd = g_dinv[gw];
    bool act = lane < 20;
    size_t fo = (size_t)(lane * 2);
    float ax = 0.f, ay = 0.f;

    for (int j0 = beg; j0 < end; j0 += 32) {
        int n = min(32, end - j0);
        int sj = 0; float wj = 0.f;
        if (lane < n) { sj = g_csr[j0 + lane]; wj = g_dinv[sj] * dd; }
        int jj = 0;
        for (; jj + 4 <= n; jj += 4) {
            int   s0 = __shfl_sync(0xffffffffu, sj, jj);
            int   s1 = __shfl_sync(0xffffffffu, sj, jj + 1);
            int   s2 = __shfl_sync(0xffffffffu, sj, jj + 2);
            int   s3 = __shfl_sync(0xffffffffu, sj, jj + 3);
            float w0 = __shfl_sync(0xffffffffu, wj, jj);
            float w1 = __shfl_sync(0xffffffffu, wj, jj + 1);
            float w2 = __shfl_sync(0xffffffffu, wj, jj + 2);
            float w3 = __shfl_sync(0xffffffffu, wj, jj + 3);
            if (act) {
                float2 v0 = *(const float2*)(g_h2 + (size_t)s0 * N_CLASS + fo);
                float2 v1 = *(const float2*)(g_h2 + (size_t)s1 * N_CLASS + fo);
                float2 v2 = *(const float2*)(g_h2 + (size_t)s2 * N_CLASS + fo);
                float2 v3 = *(const float2*)(g_h2 + (size_t)s3 * N_CLASS + fo);
                ax += w0 * v0.x; ay += w0 * v0.y;
                ax += w1 * v1.x; ay += w1 * v1.y;
                ax += w2 * v2.x; ay += w2 * v2.y;
                ax += w3 * v3.x; ay += w3 * v3.y;
            }
        }
        for (; jj < n; jj++) {
            int   s = __shfl_sync(0xffffffffu, sj, jj);
            float w = __shfl_sync(0xffffffffu, wj, jj);
            if (act) {
                float2 v = *(const float2*)(g_h2 + (size_t)s * N_CLASS + fo);
                ax += w * v.x; ay += w * v.y;
            }
        }
    }
    if (act) {
        float2 hv = *(const float2*)(g_h2 + (size_t)gw * N_CLASS + fo);
        float d2 = dd * dd;
        ax += d2 * hv.x; ay += d2 * hv.y;
        float2 bb = *(const float2*)(b2 + fo);
        ax += bb.x; ay += bb.y;
    }
    // softmax over 40 values spread across 20 lanes x 2
    float m = act ? fmaxf(ax, ay) : -3.4e38f;
    #pragma unroll
    for (int o = 16; o; o >>= 1)
        m = fmaxf(m, __shfl_xor_sync(0xffffffffu, m, o));
    float e0 = act ? expf(ax - m) : 0.f;
    float e1 = act ? expf(ay - m) : 0.f;
    float s = e0 + e1;
    #pragma unroll
    for (int o = 16; o; o >>= 1)
        s += __shfl_xor_sync(0xffffffffu, s, o);
    float inv = 1.f / s;
    if (act)
        *(float2*)(out + (size_t)gw * N_CLASS + fo) = make_float2(e0 * inv, e1 * inv);
}

// ---------------- launch -----------------------------------------------------
extern "C" void kernel_launch(void* const* d_in, const int* in_sizes, int n_in,
                              void* d_out, int out_size)
{
    const float* x   = (const float*)d_in[0];
    const void*  ei  = d_in[1];
    const float* W1  = (const float*)d_in[2];
    const float* b1  = (const float*)d_in[3];
    const float* W2  = (const float*)d_in[4];
    const float* b2  = (const float*)d_in[5];
    float* out = (float*)d_out;

    int N = in_sizes[0] / N_FEAT;   // 100000
    int E = in_sizes[1] / 2;        // 3200000

    detect_kernel<<<1, 256>>>((const int*)ei, E);
    zero_kernel<<<(N + 255) / 256, 256>>>();
    convert_count_kernel<<<(E + 255) / 256, 256>>>(ei, E);

    scan1_kernel<<<NB_SCAN, SCAN_B>>>();
    scan2_kernel<<<1, 256>>>();
    scan3_kernel<<<(N + 255) / 256, 256>>>(E);

    bin_kernel<<<(E + 255) / 256, 256>>>(E);

    gemm1_kernel<<<(N + BM - 1) / BM, 256>>>(x, W1, N);

    int warps_grid = (N * 32 + 255) / 256;
    gather1_kernel<<<warps_grid, 256>>>(b1, N);

    layer2_kernel<<<(N + 31) / 32, 160>>>(W2, N);

    gather2_kernel<<<warps_grid, 256>>>(b2, out, N);
}

// round 7
// speedup vs baseline: 1.8225x; 1.5121x over previous
#include <cuda_runtime.h>
#include <cuda_bf16.h>
#include <cstdint>
#include <cstddef>

#define N_NODES 100000
#define N_FEAT  512
#define HIDDEN  64
#define N_CLASS 40
#define MAX_E   3200000
#define SCAN_B  512
#define NB_SCAN ((N_NODES + SCAN_B - 1) / SCAN_B)   // 196

typedef unsigned long long ull;

// ---------------- scratch (device globals; no allocations allowed) ----------
__device__ float g_dinv  [N_NODES];
__device__ float g_h1    [(size_t)N_NODES * HIDDEN];
__device__ float g_a     [(size_t)N_NODES * HIDDEN];
__device__ float g_h2    [(size_t)N_NODES * N_CLASS];
__device__ int   g_src   [MAX_E];
__device__ int   g_dst   [MAX_E];
__device__ int   g_csr   [MAX_E];
__device__ int   g_cnt   [N_NODES];
__device__ int   g_cur   [N_NODES];
__device__ int   g_rowptr[N_NODES + 1];
__device__ int   g_bsum  [NB_SCAN];
__device__ int   g_is64;
// split+transposed W1 (n-major: [HIDDEN][N_FEAT])
__device__ __nv_bfloat16 g_w1t_h[HIDDEN * N_FEAT];
__device__ __nv_bfloat16 g_w1t_l[HIDDEN * N_FEAT];

// ---------------- mma helper ------------------------------------------------
__device__ __forceinline__ void mma16816(float* d, const uint32_t* a,
                                         const uint32_t* b) {
    asm volatile(
        "mma.sync.aligned.m16n8k16.row.col.f32.bf16.bf16.f32 "
        "{%0,%1,%2,%3}, {%4,%5,%6,%7}, {%8,%9}, {%0,%1,%2,%3};"
        : "+f"(d[0]), "+f"(d[1]), "+f"(d[2]), "+f"(d[3])
        : "r"(a[0]), "r"(a[1]), "r"(a[2]), "r"(a[3]),
          "r"(b[0]), "r"(b[1]));
}

// ---------------- dtype detection: int64 vs int32 edge_index ----------------
__global__ void detect_kernel(const int* __restrict__ ei, int E) {
    __shared__ int any_nonzero;
    if (threadIdx.x == 0) any_nonzero = 0;
    __syncthreads();
    int nchk = E < 2048 ? E : 2048;
    for (int i = threadIdx.x; i < nchk; i += blockDim.x)
        if (ei[2 * i + 1] != 0) any_nonzero = 1;
    __syncthreads();
    if (threadIdx.x == 0) g_is64 = (any_nonzero == 0) ? 1 : 0;
}

__global__ void zero_kernel() {
    int i = blockIdx.x * blockDim.x + threadIdx.x;
    if (i < N_NODES) { g_cnt[i] = 0; g_cur[i] = 0; }
}

// ---------------- split + transpose W1 --------------------------------------
__global__ void w1split_kernel(const float* __restrict__ W1) {
    int i = blockIdx.x * blockDim.x + threadIdx.x;
    if (i >= N_FEAT * HIDDEN) return;
    int k = i >> 6, n = i & 63;
    float w = W1[i];
    __nv_bfloat16 h = __float2bfloat16_rn(w);
    __nv_bfloat16 l = __float2bfloat16_rn(w - __bfloat162float(h));
    g_w1t_h[n * N_FEAT + k] = h;
    g_w1t_l[n * N_FEAT + k] = l;
}

// ---------------- convert edges + count in-degree ---------------------------
__global__ void convert_count_kernel(const void* __restrict__ ei, int E) {
    int e = blockIdx.x * blockDim.x + threadIdx.x;
    if (e >= E) return;
    int s, d;
    if (g_is64) {
        const long long* p = (const long long*)ei;
        s = (int)p[e]; d = (int)p[(size_t)E + e];
    } else {
        const int* p = (const int*)ei;
        s = p[e]; d = p[(size_t)E + e];
    }
    g_src[e] = s;
    g_dst[e] = d;
    atomicAdd(&g_cnt[d], 1);
}

// ---------------- 3-pass exclusive scan of g_cnt -> g_rowptr ----------------
__global__ void scan1_kernel() {
    __shared__ int s[SCAN_B];
    int b = blockIdx.x, t = threadIdx.x, i = b * SCAN_B + t;
    int v = (i < N_NODES) ? g_cnt[i] : 0;
    s[t] = v; __syncthreads();
    #pragma unroll
    for (int o = 1; o < SCAN_B; o <<= 1) {
        int add = (t >= o) ? s[t - o] : 0;
        __syncthreads();
        s[t] += add;
        __syncthreads();
    }
    if (i < N_NODES) g_rowptr[i] = s[t] - v;       // local exclusive
    if (t == SCAN_B - 1) g_bsum[b] = s[t];
}
__global__ void scan2_kernel() {
    __shared__ int s[256];
    int t = threadIdx.x;
    int v = (t < NB_SCAN) ? g_bsum[t] : 0;
    s[t] = v; __syncthreads();
    #pragma unroll
    for (int o = 1; o < 256; o <<= 1) {
        int add = (t >= o) ? s[t - o] : 0;
        __syncthreads();
        s[t] += add;
        __syncthreads();
    }
    if (t < NB_SCAN) g_bsum[t] = s[t] - v;         // exclusive block offsets
}
__global__ void scan3_kernel(int E) {
    int i = blockIdx.x * blockDim.x + threadIdx.x;
    if (i < N_NODES) {
        g_rowptr[i] += g_bsum[i / SCAN_B];
        g_dinv[i] = rsqrtf((float)g_cnt[i] + 1.0f);  // +1 self loop
    }
    if (i == 0) g_rowptr[N_NODES] = E;
}

// ---------------- bin edges into CSR ----------------------------------------
__global__ void bin_kernel(int E) {
    int e = blockIdx.x * blockDim.x + threadIdx.x;
    if (e >= E) return;
    int d = g_dst[e];
    int p = atomicAdd(&g_cur[d], 1);
    g_csr[g_rowptr[d] + p] = g_src[e];
}

// ---------------- GEMM1 (tensor core, split-bf16): h1 = x @ W1 --------------
// 128 nodes x 64 cols per block, 256 threads (8 warps), k-chunks of 32.
// acc = xh@wh + xl@wh + xh@wl  (drops only ~2^-16 xl@wl term)
#define GBM  128
#define GBK  32
#define ASTR 40   // padded smem stride (bf16) -> conflict-free fragment loads
__global__ __launch_bounds__(256) void gemm1_mma_kernel(
    const float* __restrict__ x, int N)
{
    __shared__ __nv_bfloat16 Ah[GBM][ASTR];
    __shared__ __nv_bfloat16 Al[GBM][ASTR];
    __shared__ __nv_bfloat16 Bh[HIDDEN][ASTR];
    __shared__ __nv_bfloat16 Bl[HIDDEN][ASTR];

    int tid  = threadIdx.x;
    int lane = tid & 31, warp = tid >> 5;
    int g    = lane >> 2, tig = lane & 3;
    int nb   = blockIdx.x * GBM;

    float acc[8][4];
    #pragma unroll
    for (int i = 0; i < 8; i++)
        #pragma unroll
        for (int j = 0; j < 4; j++) acc[i][j] = 0.f;

    for (int kc = 0; kc < N_FEAT; kc += GBK) {
        // ---- x tile: 128 rows x 32 k, fp32 -> bf16 hi/lo
        #pragma unroll
        for (int l = 0; l < 4; l++) {
            int e = tid + l * 256;
            int r = e >> 3, c4 = e & 7;
            float4 v = make_float4(0.f, 0.f, 0.f, 0.f);
            int node = nb + r;
            if (node < N)
                v = *(const float4*)(x + (size_t)node * N_FEAT + kc + c4 * 4);
            float2 p0 = make_float2(v.x, v.y);
            float2 p1 = make_float2(v.z, v.w);
            __nv_bfloat162 h0 = __float22bfloat162_rn(p0);
            __nv_bfloat162 h1 = __float22bfloat162_rn(p1);
            float2 hf0 = __bfloat1622float2(h0);
            float2 hf1 = __bfloat1622float2(h1);
            __nv_bfloat162 l0 = __float22bfloat162_rn(
                make_float2(p0.x - hf0.x, p0.y - hf0.y));
            __nv_bfloat162 l1 = __float22bfloat162_rn(
                make_float2(p1.x - hf1.x, p1.y - hf1.y));
            *(__nv_bfloat162*)&Ah[r][c4 * 4]     = h0;
            *(__nv_bfloat162*)&Ah[r][c4 * 4 + 2] = h1;
            *(__nv_bfloat162*)&Al[r][c4 * 4]     = l0;
            *(__nv_bfloat162*)&Al[r][c4 * 4 + 2] = l1;
        }
        // ---- W tiles: 64 n-rows x 32 k (pre-split, n-major in gmem)
        {
            int r = tid >> 2, co = (tid & 3) * 8;
            uint4 vh = *(const uint4*)(g_w1t_h + (size_t)r * N_FEAT + kc + co);
            uint4 vl = *(const uint4*)(g_w1t_l + (size_t)r * N_FEAT + kc + co);
            *(uint2*)&Bh[r][co]     = make_uint2(vh.x, vh.y);
            *(uint2*)&Bh[r][co + 4] = make_uint2(vh.z, vh.w);
            *(uint2*)&Bl[r][co]     = make_uint2(vl.x, vl.y);
            *(uint2*)&Bl[r][co + 4] = make_uint2(vl.z, vl.w);
        }
        __syncthreads();

        #pragma unroll
        for (int ks = 0; ks < GBK; ks += 16) {
            int r0 = warp * 16 + g;
            uint32_t ah[4], al[4];
            ah[0] = *(const uint32_t*)&Ah[r0][ks + tig * 2];
            ah[1] = *(const uint32_t*)&Ah[r0 + 8][ks + tig * 2];
            ah[2] = *(const uint32_t*)&Ah[r0][ks + tig * 2 + 8];
            ah[3] = *(const uint32_t*)&Ah[r0 + 8][ks + tig * 2 + 8];
            al[0] = *(const uint32_t*)&Al[r0][ks + tig * 2];
            al[1] = *(const uint32_t*)&Al[r0 + 8][ks + tig * 2];
            al[2] = *(const uint32_t*)&Al[r0][ks + tig * 2 + 8];
            al[3] = *(const uint32_t*)&Al[r0 + 8][ks + tig * 2 + 8];
            #pragma unroll
            for (int nt = 0; nt < 8; nt++) {
                int n0 = nt * 8 + g;
                uint32_t bh[2], bl[2];
                bh[0] = *(const uint32_t*)&Bh[n0][ks + tig * 2];
                bh[1] = *(const uint32_t*)&Bh[n0][ks + tig * 2 + 8];
                bl[0] = *(const uint32_t*)&Bl[n0][ks + tig * 2];
                bl[1] = *(const uint32_t*)&Bl[n0][ks + tig * 2 + 8];
                mma16816(acc[nt], ah, bh);
                mma16816(acc[nt], al, bh);
                mma16816(acc[nt], ah, bl);
            }
        }
        __syncthreads();
    }

    // ---- epilogue: fragment rows g, g+8 of this warp's 16-row slab
    int r0 = nb + warp * 16 + g;
    int r1 = r0 + 8;
    #pragma unroll
    for (int nt = 0; nt < 8; nt++) {
        int c = nt * 8 + tig * 2;
        if (r0 < N)
            *(float2*)(g_h1 + (size_t)r0 * HIDDEN + c) =
                make_float2(acc[nt][0], acc[nt][1]);
        if (r1 < N)
            *(float2*)(g_h1 + (size_t)r1 * HIDDEN + c) =
                make_float2(acc[nt][2], acc[nt][3]);
    }
}

// ------ gather layer 1: a = relu(sum_{s->d} w*h1[s] + dinv^2*h1[d] + b1) ----
// One warp per dst node; lane covers feats [2*lane, 2*lane+1].
__global__ __launch_bounds__(256) void gather1_kernel(
    const float* __restrict__ b1, int N)
{
    int gw   = (blockIdx.x * blockDim.x + threadIdx.x) >> 5;
    int lane = threadIdx.x & 31;
    if (gw >= N) return;
    int beg = g_rowptr[gw], end = g_rowptr[gw + 1];
    float dd = g_dinv[gw];
    float ax = 0.f, ay = 0.f;

    for (int j0 = beg; j0 < end; j0 += 32) {
        int n = min(32, end - j0);
        int sj = 0; float wj = 0.f;
        if (lane < n) { sj = g_csr[j0 + lane]; wj = g_dinv[sj] * dd; }
        int jj = 0;
        for (; jj + 8 <= n; jj += 8) {
            int s[8]; float w[8];
            #pragma unroll
            for (int q = 0; q < 8; q++) {
                s[q] = __shfl_sync(0xffffffffu, sj, jj + q);
                w[q] = __shfl_sync(0xffffffffu, wj, jj + q);
            }
            float2 v[8];
            #pragma unroll
            for (int q = 0; q < 8; q++)
                v[q] = *(const float2*)(g_h1 + (size_t)s[q] * HIDDEN + lane * 2);
            #pragma unroll
            for (int q = 0; q < 8; q++) {
                ax += w[q] * v[q].x; ay += w[q] * v[q].y;
            }
        }
        for (; jj < n; jj++) {
            int   s = __shfl_sync(0xffffffffu, sj, jj);
            float w = __shfl_sync(0xffffffffu, wj, jj);
            float2 v = *(const float2*)(g_h1 + (size_t)s * HIDDEN + lane * 2);
            ax += w * v.x; ay += w * v.y;
        }
    }
    float2 hv = *(const float2*)(g_h1 + (size_t)gw * HIDDEN + lane * 2);
    float d2 = dd * dd;
    ax += d2 * hv.x; ay += d2 * hv.y;
    float2 bb = *(const float2*)(b1 + lane * 2);
    ax = fmaxf(ax + bb.x, 0.f);
    ay = fmaxf(ay + bb.y, 0.f);
    *(float2*)(g_a + (size_t)gw * HIDDEN + lane * 2) = make_float2(ax, ay);
}

// ---------------- layer 2 GEMM: h2 = a @ W2 (64x40) -------------------------
__global__ __launch_bounds__(160) void layer2_kernel(
    const float* __restrict__ W2, int N)
{
    __shared__ float a  [32 * 64];
    __shared__ float w2s[64 * 40];
    int tid = threadIdx.x;
    int nb  = blockIdx.x * 32;

    for (int i = tid; i < 64 * 40; i += 160) w2s[i] = W2[i];
    __syncthreads();

    for (int i = tid; i < 32 * 64; i += 160) {
        int r = i >> 6, k = i & 63;
        int node = nb + r;
        a[i] = (node < N) ? g_a[(size_t)node * 64 + k] : 0.f;
    }
    __syncthreads();

    int c = tid % 40;
    int g = tid / 40;
    float acc[8];
    #pragma unroll
    for (int i = 0; i < 8; i++) acc[i] = 0.f;
    #pragma unroll
    for (int k = 0; k < 64; k++) {
        float w = w2s[k * 40 + c];
        #pragma unroll
        for (int i = 0; i < 8; i++)
            acc[i] += a[(g + i * 4) * 64 + k] * w;
    }
    #pragma unroll
    for (int i = 0; i < 8; i++) {
        int node = nb + g + i * 4;
        if (node < N) g_h2[(size_t)node * N_CLASS + c] = acc[i];
    }
}

// ------ gather layer 2 + b2 + softmax (fused final) -------------------------
// One warp per dst node; lanes 0..19 each cover feats [2*lane, 2*lane+1].
__global__ __launch_bounds__(256) void gather2_kernel(
    const float* __restrict__ b2, float* __restrict__ out, int N)
{
    int gw   = (blockIdx.x * blockDim.x + threadIdx.x) >> 5;
    int lane = threadIdx.x & 31;
    if (gw >= N) return;
    int beg = g_rowptr[gw], end = g_rowptr[gw + 1];
    float dd = g_dinv[gw];
    bool act = lane < 20;
    size_t fo = (size_t)(lane * 2);
    float ax = 0.f, ay = 0.f;

    for (int j0 = beg; j0 < end; j0 += 32) {
        int n = min(32, end - j0);
        int sj = 0; float wj = 0.f;
        if (lane < n) { sj = g_csr[j0 + lane]; wj = g_dinv[sj] * dd; }
        int jj = 0;
        for (; jj + 8 <= n; jj += 8) {
            int s[8]; float w[8];
            #pragma unroll
            for (int q = 0; q < 8; q++) {
                s[q] = __shfl_sync(0xffffffffu, sj, jj + q);
                w[q] = __shfl_sync(0xffffffffu, wj, jj + q);
            }
            if (act) {
                float2 v[8];
                #pragma unroll
                for (int q = 0; q < 8; q++)
                    v[q] = *(const float2*)(g_h2 + (size_t)s[q] * N_CLASS + fo);
                #pragma unroll
                for (int q = 0; q < 8; q++) {
                    ax += w[q] * v[q].x; ay += w[q] * v[q].y;
                }
            }
        }
        for (; jj < n; jj++) {
            int   s = __shfl_sync(0xffffffffu, sj, jj);
            float w = __shfl_sync(0xffffffffu, wj, jj);
            if (act) {
                float2 v = *(const float2*)(g_h2 + (size_t)s * N_CLASS + fo);
                ax += w * v.x; ay += w * v.y;
            }
        }
    }
    if (act) {
        float2 hv = *(const float2*)(g_h2 + (size_t)gw * N_CLASS + fo);
        float d2 = dd * dd;
        ax += d2 * hv.x; ay += d2 * hv.y;
        float2 bb = *(const float2*)(b2 + fo);
        ax += bb.x; ay += bb.y;
    }
    // softmax over 40 values spread across 20 lanes x 2
    float m = act ? fmaxf(ax, ay) : -3.4e38f;
    #pragma unroll
    for (int o = 16; o; o >>= 1)
        m = fmaxf(m, __shfl_xor_sync(0xffffffffu, m, o));
    float e0 = act ? expf(ax - m) : 0.f;
    float e1 = act ? expf(ay - m) : 0.f;
    float s = e0 + e1;
    #pragma unroll
    for (int o = 16; o; o >>= 1)
        s += __shfl_xor_sync(0xffffffffu, s, o);
    float inv = 1.f / s;
    if (act)
        *(float2*)(out + (size_t)gw * N_CLASS + fo) = make_float2(e0 * inv, e1 * inv);
}

// ---------------- launch -----------------------------------------------------
extern "C" void kernel_launch(void* const* d_in, const int* in_sizes, int n_in,
                              void* d_out, int out_size)
{
    const float* x   = (const float*)d_in[0];
    const void*  ei  = d_in[1];
    const float* W1  = (const float*)d_in[2];
    const float* b1  = (const float*)d_in[3];
    const float* W2  = (const float*)d_in[4];
    const float* b2  = (const float*)d_in[5];
    float* out = (float*)d_out;

    int N = in_sizes[0] / N_FEAT;   // 100000
    int E = in_sizes[1] / 2;        // 3200000

    detect_kernel<<<1, 256>>>((const int*)ei, E);
    zero_kernel<<<(N + 255) / 256, 256>>>();
    w1split_kernel<<<(N_FEAT * HIDDEN + 255) / 256, 256>>>(W1);
    convert_count_kernel<<<(E + 255) / 256, 256>>>(ei, E);

    scan1_kernel<<<NB_SCAN, SCAN_B>>>();
    scan2_kernel<<<1, 256>>>();
    scan3_kernel<<<(N + 255) / 256, 256>>>(E);

    bin_kernel<<<(E + 255) / 256, 256>>>(E);

    gemm1_mma_kernel<<<(N + GBM - 1) / GBM, 256>>>(x, N);

    int warps_grid = (N * 32 + 255) / 256;
    gather1_kernel<<<warps_grid, 256>>>(b1, N);

    layer2_kernel<<<(N + 31) / 32, 160>>>(W2, N);

    gather2_kernel<<<warps_grid, 256>>>(b2, out, N);
}